// round 5
// baseline (speedup 1.0000x reference)
#include <cuda_runtime.h>
#include <math.h>

// Problem constants
#define NB 4
#define NT 2048
#define NC 1024
#define NH 16
#define ND 64
#define NM (NB * NT)      // 8192
#define NQKV (3 * NC)     // 3072

// Scratch (device globals — no runtime allocation allowed)
__device__ float g_q  [(size_t)NB * NH * NT * ND];  // [B,H,T,Dh]
__device__ float g_kT [(size_t)NB * NH * ND * NT];  // [B,H,Dh,T]  (K transposed for conflict-free smem tiles)
__device__ float g_v  [(size_t)NB * NH * NT * ND];  // [B,H,T,Dh]
__device__ float g_att[(size_t)NB * NT * NC];       // [B,T,C] attention output (pre out-proj)

// ---------------------------------------------------------------------------
// SGEMM: C[M,N] = A[M,1024] @ W[1024,N] + bias
// 128x128 block tile, BK=8, 256 threads, 8x8 microtile (split 4+4 for
// conflict-free LDS.128).
// MODE 0: plain output to `out` (out projection, A = g_att)
// MODE 1: QKV scatter into g_q / g_kT / g_v
// ---------------------------------------------------------------------------
template <int N, int MODE>
__global__ __launch_bounds__(256)
void sgemm_kernel(const float* __restrict__ A_in, const float* __restrict__ W,
                  const float* __restrict__ bias, float* __restrict__ out)
{
    __shared__ float As[8][128];   // As[k][m]
    __shared__ float Bs[8][128];   // Bs[k][n]

    const int tid = threadIdx.x;
    const int bm = blockIdx.y, bn = blockIdx.x;
    const int K = NC;
    const int ty = tid >> 4, tx = tid & 15;

    const int a_row = tid >> 1;            // 0..127
    const int a_col = (tid & 1) * 4;       // 0 or 4
    const int b_row = tid >> 5;            // 0..7
    const int b_col = (tid & 31) * 4;      // 0..124

    const float* A  = (MODE == 0) ? g_att : A_in;
    const float* Ap = A + (size_t)(bm * 128 + a_row) * K + a_col;
    const float* Bp = W + (size_t)b_row * N + bn * 128 + b_col;

    float acc[8][8];
#pragma unroll
    for (int i = 0; i < 8; i++)
#pragma unroll
        for (int j = 0; j < 8; j++) acc[i][j] = 0.0f;

    for (int k0 = 0; k0 < K; k0 += 8) {
        float4 av = *(const float4*)(Ap + k0);
        float4 bv = *(const float4*)(Bp + (size_t)k0 * N);
        __syncthreads();
        As[a_col + 0][a_row] = av.x;
        As[a_col + 1][a_row] = av.y;
        As[a_col + 2][a_row] = av.z;
        As[a_col + 3][a_row] = av.w;
        *(float4*)&Bs[b_row][b_col] = bv;
        __syncthreads();
#pragma unroll
        for (int kk = 0; kk < 8; kk++) {
            float4 a0 = *(const float4*)&As[kk][ty * 4];
            float4 a1 = *(const float4*)&As[kk][64 + ty * 4];
            float4 b0 = *(const float4*)&Bs[kk][tx * 4];
            float4 b1 = *(const float4*)&Bs[kk][64 + tx * 4];
            float a[8] = {a0.x, a0.y, a0.z, a0.w, a1.x, a1.y, a1.z, a1.w};
            float b[8] = {b0.x, b0.y, b0.z, b0.w, b1.x, b1.y, b1.z, b1.w};
#pragma unroll
            for (int i = 0; i < 8; i++)
#pragma unroll
                for (int j = 0; j < 8; j++)
                    acc[i][j] += a[i] * b[j];
        }
    }

    const int rb0 = bm * 128 + ty * 4;
    const int rb1 = bm * 128 + 64 + ty * 4;

#pragma unroll
    for (int jg = 0; jg < 2; jg++) {
        const int cb = bn * 128 + jg * 64 + tx * 4;
        const float bz0 = bias[cb + 0];
        const float bz1 = bias[cb + 1];
        const float bz2 = bias[cb + 2];
        const float bz3 = bias[cb + 3];

        if (MODE == 0) {
#pragma unroll
            for (int ig = 0; ig < 2; ig++)
#pragma unroll
                for (int i = 0; i < 4; i++) {
                    const int m = (ig == 0 ? rb0 : rb1) + i;
                    float4 v = make_float4(acc[ig * 4 + i][jg * 4 + 0] + bz0,
                                           acc[ig * 4 + i][jg * 4 + 1] + bz1,
                                           acc[ig * 4 + i][jg * 4 + 2] + bz2,
                                           acc[ig * 4 + i][jg * 4 + 3] + bz3);
                    *(float4*)&out[(size_t)m * N + cb] = v;
                }
        } else {
            const int part = cb >> 10;          // 0=q 1=k 2=v
            const int cc   = cb & (NC - 1);
            const int h    = cc >> 6;
            const int d0   = cc & 63;
#pragma unroll
            for (int ig = 0; ig < 2; ig++)
#pragma unroll
                for (int i = 0; i < 4; i++) {
                    const int m  = (ig == 0 ? rb0 : rb1) + i;
                    const int bb = m >> 11;
                    const int t  = m & (NT - 1);
                    const int bh = bb * NH + h;
                    const float v0 = acc[ig * 4 + i][jg * 4 + 0] + bz0;
                    const float v1 = acc[ig * 4 + i][jg * 4 + 1] + bz1;
                    const float v2 = acc[ig * 4 + i][jg * 4 + 2] + bz2;
                    const float v3 = acc[ig * 4 + i][jg * 4 + 3] + bz3;
                    if (part == 1) {
                        // K transposed: [bh][d][t]
                        const size_t base = ((size_t)bh * ND + d0) * NT + t;
                        g_kT[base]          = v0;
                        g_kT[base + NT]     = v1;
                        g_kT[base + 2 * NT] = v2;
                        g_kT[base + 3 * NT] = v3;
                    } else {
                        float* dst = (part == 0) ? g_q : g_v;
                        *(float4*)&dst[((size_t)bh * NT + t) * ND + d0] =
                            make_float4(v0, v1, v2, v3);
                    }
                }
        }
    }
}

// ---------------------------------------------------------------------------
// Flash attention (fp32, causal). One block = one (b,h) x 128-row q tile.
// Iterates 64-key tiles up to the diagonal. 128 threads, 8x8 microtiles.
// Softmax in exp2 domain (Q pre-scaled by (1/8)*log2(e)).
// ---------------------------------------------------------------------------
#define FLASH_SMEM_FLOATS (64 * 128 + 64 * 64 + 64 * 64 + 64 * 132)
#define FLASH_SMEM_BYTES  (FLASH_SMEM_FLOATS * 4)

__global__ __launch_bounds__(128)
void flash_kernel()
{
    extern __shared__ float sm[];
    float* Qst = sm;                         // [64 d][128 r]
    float* Kst = Qst + 64 * 128;             // [64 d][64 key]
    float* Vs  = Kst + 64 * 64;              // [64 key][64 d]
    float* Pst = Vs + 64 * 64;               // [64 key][132 pad r]

    const int tid = threadIdx.x;
    const int tx = tid & 7;                  // 8 col groups
    const int ty = tid >> 3;                 // 16 row groups
    const int qt = blockIdx.x;
    const int bh = blockIdx.y;
    const int q0 = qt * 128;

    const float SCALE = 0.125f * 1.44269504088896340736f;   // (1/sqrt(64)) * log2(e)

    const float* Qg = g_q  + ((size_t)bh * NT + q0) * ND;
    const float* Kg = g_kT + (size_t)bh * ND * NT;
    const float* Vg = g_v  + (size_t)bh * NT * ND;

    // Load Q tile transposed + scaled: thread r = tid owns one q row.
    {
        const int r = tid;
#pragma unroll
        for (int d4 = 0; d4 < 16; d4++) {
            float4 v = *(const float4*)(Qg + (size_t)r * ND + d4 * 4);
            Qst[(d4 * 4 + 0) * 128 + r] = v.x * SCALE;
            Qst[(d4 * 4 + 1) * 128 + r] = v.y * SCALE;
            Qst[(d4 * 4 + 2) * 128 + r] = v.z * SCALE;
            Qst[(d4 * 4 + 3) * 128 + r] = v.w * SCALE;
        }
    }

    float m_i[8], l_i[8], o[8][8];
#pragma unroll
    for (int i = 0; i < 8; i++) {
        m_i[i] = -1e30f;
        l_i[i] = 0.0f;
#pragma unroll
        for (int j = 0; j < 8; j++) o[i][j] = 0.0f;
    }

    const int nkt = 2 * qt + 2;
    for (int jt = 0; jt < nkt; jt++) {
        const int k0 = jt * 64;
        __syncthreads();   // prev PV done / Q tile visible

        // Load K tile [d][key] (coalesced from g_kT), V tile [key][d]
#pragma unroll
        for (int p = 0; p < 8; p++) {
            const int lin = p * 512 + tid * 4;        // 0..4095
            const int d = lin >> 6, kq = lin & 63;
            float4 kv = *(const float4*)(Kg + (size_t)d * NT + k0 + kq);
            *(float4*)&Kst[d * 64 + kq] = kv;
            float4 vv = *(const float4*)(Vg + (size_t)k0 * ND + lin);
            *(float4*)&Vs[lin] = vv;
        }
        __syncthreads();

        // S = Qs^T @ Ks  (8x8 per thread)
        float s[8][8];
#pragma unroll
        for (int i = 0; i < 8; i++)
#pragma unroll
            for (int j = 0; j < 8; j++) s[i][j] = 0.0f;

#pragma unroll 8
        for (int kk = 0; kk < 64; kk++) {
            float4 qa = *(const float4*)&Qst[kk * 128 + ty * 4];
            float4 qb = *(const float4*)&Qst[kk * 128 + 64 + ty * 4];
            float4 ka = *(const float4*)&Kst[kk * 64 + tx * 4];
            float4 kb = *(const float4*)&Kst[kk * 64 + 32 + tx * 4];
            float a[8] = {qa.x, qa.y, qa.z, qa.w, qb.x, qb.y, qb.z, qb.w};
            float b[8] = {ka.x, ka.y, ka.z, ka.w, kb.x, kb.y, kb.z, kb.w};
#pragma unroll
            for (int i = 0; i < 8; i++)
#pragma unroll
                for (int j = 0; j < 8; j++)
                    s[i][j] += a[i] * b[j];
        }

        // Causal mask (only the two tiles overlapping the diagonal)
        if (jt >= 2 * qt) {
#pragma unroll
            for (int i = 0; i < 8; i++) {
                const int q = q0 + ((i < 4) ? (ty * 4 + i) : (64 + ty * 4 + i - 4));
#pragma unroll
                for (int j = 0; j < 8; j++) {
                    const int kc = k0 + ((j < 4) ? (tx * 4 + j) : (32 + tx * 4 + j - 4));
                    if (kc > q) s[i][j] = -1e30f;
                }
            }
        }

        // Online softmax update (row stats shared across the 8 tx lanes)
#pragma unroll
        for (int i = 0; i < 8; i++) {
            float mx = s[i][0];
#pragma unroll
            for (int j = 1; j < 8; j++) mx = fmaxf(mx, s[i][j]);
            mx = fmaxf(mx, __shfl_xor_sync(0xffffffffu, mx, 1));
            mx = fmaxf(mx, __shfl_xor_sync(0xffffffffu, mx, 2));
            mx = fmaxf(mx, __shfl_xor_sync(0xffffffffu, mx, 4));
            const float mnew = fmaxf(m_i[i], mx);
            const float fac  = exp2f(m_i[i] - mnew);
            float rs = 0.0f;
#pragma unroll
            for (int j = 0; j < 8; j++) {
                s[i][j] = exp2f(s[i][j] - mnew);
                rs += s[i][j];
            }
            rs += __shfl_xor_sync(0xffffffffu, rs, 1);
            rs += __shfl_xor_sync(0xffffffffu, rs, 2);
            rs += __shfl_xor_sync(0xffffffffu, rs, 4);
            l_i[i] = l_i[i] * fac + rs;
            m_i[i] = mnew;
#pragma unroll
            for (int j = 0; j < 8; j++) o[i][j] *= fac;
        }

        // Write P transposed: Pst[key][row]
#pragma unroll
        for (int j = 0; j < 8; j++) {
            const int col = (j < 4) ? (tx * 4 + j) : (32 + tx * 4 + (j - 4));
            float4 v0 = make_float4(s[0][j], s[1][j], s[2][j], s[3][j]);
            float4 v1 = make_float4(s[4][j], s[5][j], s[6][j], s[7][j]);
            *(float4*)&Pst[col * 132 + ty * 4]      = v0;
            *(float4*)&Pst[col * 132 + 64 + ty * 4] = v1;
        }
        __syncthreads();

        // O += P @ V
#pragma unroll 8
        for (int kk = 0; kk < 64; kk++) {
            float4 pa = *(const float4*)&Pst[kk * 132 + ty * 4];
            float4 pb = *(const float4*)&Pst[kk * 132 + 64 + ty * 4];
            float4 va = *(const float4*)&Vs[kk * 64 + tx * 4];
            float4 vb = *(const float4*)&Vs[kk * 64 + 32 + tx * 4];
            float p[8] = {pa.x, pa.y, pa.z, pa.w, pb.x, pb.y, pb.z, pb.w};
            float v[8] = {va.x, va.y, va.z, va.w, vb.x, vb.y, vb.z, vb.w};
#pragma unroll
            for (int i = 0; i < 8; i++)
#pragma unroll
                for (int j = 0; j < 8; j++)
                    o[i][j] += p[i] * v[j];
        }
    }

    // Epilogue: normalize, write to g_att in [B,T,C] layout
    const int b = bh >> 4;
    const int h = bh & 15;
#pragma unroll
    for (int i = 0; i < 8; i++) {
        const int q = q0 + ((i < 4) ? (ty * 4 + i) : (64 + ty * 4 + (i - 4)));
        const float inv = 1.0f / l_i[i];
        float4 r0 = make_float4(o[i][0] * inv, o[i][1] * inv, o[i][2] * inv, o[i][3] * inv);
        float4 r1 = make_float4(o[i][4] * inv, o[i][5] * inv, o[i][6] * inv, o[i][7] * inv);
        const size_t base = ((size_t)(b * NT + q)) * NC + h * ND;
        *(float4*)&g_att[base + tx * 4]      = r0;
        *(float4*)&g_att[base + 32 + tx * 4] = r1;
    }
}

// ---------------------------------------------------------------------------
// kernel_launch
// ---------------------------------------------------------------------------
extern "C" void kernel_launch(void* const* d_in, const int* in_sizes, int n_in,
                              void* d_out, int out_size)
{
    const float* x     = (const float*)d_in[0];
    const float* w_qkv = (const float*)d_in[1];
    const float* b_qkv = (const float*)d_in[2];
    const float* w_out = (const float*)d_in[3];
    const float* b_out = (const float*)d_in[4];
    float* out = (float*)d_out;

    cudaFuncSetAttribute((const void*)flash_kernel,
                         cudaFuncAttributeMaxDynamicSharedMemorySize, FLASH_SMEM_BYTES);

    // 1) QKV projection + scatter to [B,H,T,Dh] (K transposed to [B,H,Dh,T])
    sgemm_kernel<NQKV, 1><<<dim3(NQKV / 128, NM / 128), 256>>>(x, w_qkv, b_qkv, nullptr);

    // 2) Causal flash attention -> g_att [B,T,C]
    flash_kernel<<<dim3(NT / 128, NB * NH), 128, FLASH_SMEM_BYTES>>>();

    // 3) Output projection
    sgemm_kernel<NC, 0><<<dim3(NC / 128, NM / 128), 256>>>(nullptr, w_out, b_out, out);
}

// round 10
// speedup vs baseline: 1.3707x; 1.3707x over previous
#include <cuda_runtime.h>
#include <cuda_bf16.h>
#include <stdint.h>
#include <math.h>

// Problem constants
#define NB 4
#define NT 2048
#define NC 1024
#define NH 16
#define ND 64
#define NM (NB * NT)      // 8192
#define NQKV (3 * NC)     // 3072

// ---------------------------------------------------------------------------
// Scratch (device globals — no runtime allocation allowed)
// ---------------------------------------------------------------------------
__device__ float g_q  [(size_t)NB * NH * NT * ND];  // [B,H,T,Dh]
__device__ float g_kT [(size_t)NB * NH * ND * NT];  // [B,H,Dh,T]
__device__ float g_v  [(size_t)NB * NH * NT * ND];  // [B,H,T,Dh]
__device__ float g_att[(size_t)NB * NT * NC];       // [B,T,C]

// bf16 split operands
__device__ __nv_bfloat16 g_ah  [(size_t)NM * NC];
__device__ __nv_bfloat16 g_al  [(size_t)NM * NC];
__device__ __nv_bfloat16 g_wqT_h[(size_t)NQKV * NC];   // w_qkv^T  [N][K]
__device__ __nv_bfloat16 g_wqT_l[(size_t)NQKV * NC];
__device__ __nv_bfloat16 g_woT_h[(size_t)NC * NC];     // w_out^T  [N][K]
__device__ __nv_bfloat16 g_woT_l[(size_t)NC * NC];
__device__ __nv_bfloat16 g_atth[(size_t)NM * NC];
__device__ __nv_bfloat16 g_attl[(size_t)NM * NC];

// ---------------------------------------------------------------------------
// PTX helpers (sm_80-class only: ldmatrix / mma.sync / cp.async — all legal
// on base sm_103 PTX target; tcgen05 is arch-'a' gated and unusable here)
// ---------------------------------------------------------------------------
__device__ __forceinline__ uint32_t smem_u32(const void* p) {
    uint32_t a;
    asm("{ .reg .u64 t; cvta.to.shared.u64 t, %1; cvt.u32.u64 %0, t; }"
        : "=r"(a) : "l"(p));
    return a;
}

__device__ __forceinline__ void ldm_x4(uint32_t* r, uint32_t addr) {
    asm volatile("ldmatrix.sync.aligned.m8n8.x4.shared.b16 {%0,%1,%2,%3}, [%4];"
                 : "=r"(r[0]), "=r"(r[1]), "=r"(r[2]), "=r"(r[3]) : "r"(addr));
}

__device__ __forceinline__ void mma_bf16(float* c, const uint32_t* a,
                                         uint32_t b0, uint32_t b1) {
    asm volatile(
        "mma.sync.aligned.m16n8k16.row.col.f32.bf16.bf16.f32 "
        "{%0,%1,%2,%3}, {%4,%5,%6,%7}, {%8,%9}, {%0,%1,%2,%3};"
        : "+f"(c[0]), "+f"(c[1]), "+f"(c[2]), "+f"(c[3])
        : "r"(a[0]), "r"(a[1]), "r"(a[2]), "r"(a[3]), "r"(b0), "r"(b1));
}

#define CP_ASYNC16(dst, src) \
    asm volatile("cp.async.cg.shared.global [%0], [%1], 16;" \
                 :: "r"(dst), "l"(src) : "memory")
#define CP_COMMIT()  asm volatile("cp.async.commit_group;" ::: "memory")
#define CP_WAIT(n)   asm volatile("cp.async.wait_group %0;" :: "n"(n) : "memory")

// ---------------------------------------------------------------------------
// Conversion kernels (fp32 -> bf16 hi/lo split)
// ---------------------------------------------------------------------------
__global__ void convert_split_kernel(const float* __restrict__ in,
                                     __nv_bfloat16* __restrict__ hi,
                                     __nv_bfloat16* __restrict__ lo, int n4)
{
    int i = blockIdx.x * blockDim.x + threadIdx.x;
    if (i >= n4) return;
    float4 v = ((const float4*)in)[i];
    __nv_bfloat16 hx = __float2bfloat16(v.x);
    __nv_bfloat16 hy = __float2bfloat16(v.y);
    __nv_bfloat16 hz = __float2bfloat16(v.z);
    __nv_bfloat16 hw = __float2bfloat16(v.w);
    ((__nv_bfloat162*)hi)[2 * i]     = __nv_bfloat162(hx, hy);
    ((__nv_bfloat162*)hi)[2 * i + 1] = __nv_bfloat162(hz, hw);
    ((__nv_bfloat162*)lo)[2 * i] =
        __nv_bfloat162(__float2bfloat16(v.x - __bfloat162float(hx)),
                       __float2bfloat16(v.y - __bfloat162float(hy)));
    ((__nv_bfloat162*)lo)[2 * i + 1] =
        __nv_bfloat162(__float2bfloat16(v.z - __bfloat162float(hz)),
                       __float2bfloat16(v.w - __bfloat162float(hw)));
}

// W [K][N] fp32  ->  Th/Tl [N][K] bf16 (transpose + split)
__global__ void transpose_split_kernel(const float* __restrict__ W,
                                       __nv_bfloat16* __restrict__ Th,
                                       __nv_bfloat16* __restrict__ Tl,
                                       int Kdim, int Ndim)
{
    __shared__ float tile[32][33];
    const int nx = blockIdx.x * 32 + threadIdx.x;
    const int ky = blockIdx.y * 32;
#pragma unroll
    for (int i = threadIdx.y; i < 32; i += 8)
        tile[i][threadIdx.x] = W[(size_t)(ky + i) * Ndim + nx];
    __syncthreads();
    const int k = ky + threadIdx.x;
#pragma unroll
    for (int i = threadIdx.y; i < 32; i += 8) {
        const int n = blockIdx.x * 32 + i;
        const float v = tile[threadIdx.x][i];
        __nv_bfloat16 h = __float2bfloat16(v);
        Th[(size_t)n * Kdim + k] = h;
        Tl[(size_t)n * Kdim + k] = __float2bfloat16(v - __bfloat162float(h));
    }
}

// ---------------------------------------------------------------------------
// mma.sync bf16-split3 GEMM: C[M,NTOT] = A[M,1024] @ B^T + bias
//   C = Ah*Bh + Ah*Bl + Al*Bh  (fp32 accumulate)
// CTA 128x128, BK=32, 256 threads (8 warps 4x2, warp tile 32x64),
// cp.async 2-stage pipeline, 80B padded smem rows (ldmatrix conflict-free).
// MODE 0: fp32 out + bias.  MODE 1: QKV scatter into g_q / g_kT / g_v.
// ---------------------------------------------------------------------------
#define TILE_B   10240               // 128 rows * 80 B
#define STAGE_B  (4 * TILE_B)        // Ah, Al, Bh, Bl
#define GEMM_SMEM (2 * STAGE_B)      // 81920 B

template <int NTOT, int MODE>
__global__ __launch_bounds__(256, 1)
void gemm_mma(const __nv_bfloat16* __restrict__ Ahg, const __nv_bfloat16* __restrict__ Alg,
              const __nv_bfloat16* __restrict__ Bhg, const __nv_bfloat16* __restrict__ Blg,
              const float* __restrict__ bias, float* __restrict__ out)
{
    extern __shared__ char smem[];
    const uint32_t sb = smem_u32(smem);
    const int tid = threadIdx.x;
    const int wid = tid >> 5, lane = tid & 31;
    const int wm = wid & 3, wn = wid >> 2;
    const int bn = blockIdx.x, bm = blockIdx.y;

    const __nv_bfloat16* srcs[4] = {Ahg, Alg, Bhg, Blg};

    float acc[2][8][4];
#pragma unroll
    for (int i = 0; i < 2; i++)
#pragma unroll
        for (int j = 0; j < 8; j++)
#pragma unroll
            for (int f = 0; f < 4; f++) acc[i][j][f] = 0.0f;

    // per-thread load slots: 512 16B-chunks per tile, 2 per thread
    const int r_ld[2]  = {tid >> 2, (tid + 256) >> 2};
    const int c_ld[2]  = {(tid & 3) * 16, (tid & 3) * 16};   // byte col within 64B row

    auto issue_loads = [&](int kc, int st) {
#pragma unroll
        for (int t4 = 0; t4 < 4; t4++) {
            const size_t rb = (t4 < 2) ? (size_t)bm * 128 : (size_t)bn * 128;
            const __nv_bfloat16* src = srcs[t4] + rb * NC + kc * 32;
            const uint32_t dst = sb + st * STAGE_B + t4 * TILE_B;
#pragma unroll
            for (int u = 0; u < 2; u++) {
                const int r = r_ld[u], cB = c_ld[u];
                CP_ASYNC16(dst + r * 80 + cB,
                           (const char*)(src + (size_t)r * NC) + cB);
            }
        }
        CP_COMMIT();
    };

    issue_loads(0, 0);

    for (int kc = 0; kc < 32; kc++) {
        const int st = kc & 1;
        __syncthreads();                 // prior compute done before refilling
        if (kc + 1 < 32) {
            issue_loads(kc + 1, st ^ 1);
            CP_WAIT(1);
        } else {
            CP_WAIT(0);
        }
        __syncthreads();

        const uint32_t stb = sb + st * STAGE_B;
        const uint32_t lrow = (lane & 15);
        const uint32_t lcol = (lane >> 4) * 16;

#pragma unroll
        for (int k16 = 0; k16 < 2; k16++) {
            const uint32_t koff = k16 * 32 + lcol;
            uint32_t aH[2][4], aL[2][4], bH[4][4], bL[4][4];
#pragma unroll
            for (int i = 0; i < 2; i++) {
                const uint32_t row = wm * 32 + i * 16 + lrow;
                ldm_x4(aH[i], stb + 0 * TILE_B + row * 80 + koff);
                ldm_x4(aL[i], stb + 1 * TILE_B + row * 80 + koff);
            }
#pragma unroll
            for (int j2 = 0; j2 < 4; j2++) {
                const uint32_t row = wn * 64 + j2 * 16 + lrow;
                ldm_x4(bH[j2], stb + 2 * TILE_B + row * 80 + koff);
                ldm_x4(bL[j2], stb + 3 * TILE_B + row * 80 + koff);
            }
#pragma unroll
            for (int i = 0; i < 2; i++)
#pragma unroll
                for (int j = 0; j < 8; j++) {
                    const int j2 = j >> 1, o = j & 1;
                    mma_bf16(acc[i][j], aH[i], bH[j2][o], bH[j2][o + 2]);
                    mma_bf16(acc[i][j], aH[i], bL[j2][o], bL[j2][o + 2]);
                    mma_bf16(acc[i][j], aL[i], bH[j2][o], bH[j2][o + 2]);
                }
        }
    }

    // Epilogue. c0,c1 -> row lane>>2, cols (lane&3)*2,+1 ; c2,c3 -> row+8
    const int rr = lane >> 2;
    const int cc = (lane & 3) * 2;
#pragma unroll
    for (int i = 0; i < 2; i++) {
#pragma unroll
        for (int j = 0; j < 8; j++) {
            const int gc = bn * 128 + wn * 64 + j * 8 + cc;
            const float bz0 = bias[gc], bz1 = bias[gc + 1];
#pragma unroll
            for (int h2 = 0; h2 < 2; h2++) {
                const int gm = bm * 128 + wm * 32 + i * 16 + h2 * 8 + rr;
                const float v0 = acc[i][j][h2 * 2 + 0] + bz0;
                const float v1 = acc[i][j][h2 * 2 + 1] + bz1;
                if (MODE == 0) {
                    *(float2*)&out[(size_t)gm * NTOT + gc] = make_float2(v0, v1);
                } else {
                    const int part = gc >> 10;          // 0=q 1=k 2=v
                    const int h  = (gc & (NC - 1)) >> 6;
                    const int d0 = gc & 63;
                    const int b  = gm >> 11;
                    const int tt = gm & (NT - 1);
                    const int bh = b * NH + h;
                    if (part == 1) {
                        const size_t kb = ((size_t)bh * ND + d0) * NT + tt;
                        g_kT[kb]      = v0;
                        g_kT[kb + NT] = v1;
                    } else {
                        float* dst = (part == 0) ? g_q : g_v;
                        *(float2*)&dst[((size_t)bh * NT + tt) * ND + d0] =
                            make_float2(v0, v1);
                    }
                }
            }
        }
    }
}

// ---------------------------------------------------------------------------
// Flash attention (fp32, causal) — unchanged (passed at rel_err 9.7e-7)
// ---------------------------------------------------------------------------
#define FLASH_SMEM_FLOATS (64 * 128 + 64 * 64 + 64 * 64 + 64 * 132)
#define FLASH_SMEM_BYTES  (FLASH_SMEM_FLOATS * 4)

__global__ __launch_bounds__(128)
void flash_kernel()
{
    extern __shared__ float sm[];
    float* Qst = sm;                         // [64 d][128 r]
    float* Kst = Qst + 64 * 128;             // [64 d][64 key]
    float* Vs  = Kst + 64 * 64;              // [64 key][64 d]
    float* Pst = Vs + 64 * 64;               // [64 key][132 pad r]

    const int tid = threadIdx.x;
    const int tx = tid & 7;
    const int ty = tid >> 3;
    const int qt = blockIdx.x;
    const int bh = blockIdx.y;
    const int q0 = qt * 128;

    const float SCALE = 0.125f * 1.44269504088896340736f;

    const float* Qg = g_q  + ((size_t)bh * NT + q0) * ND;
    const float* Kg = g_kT + (size_t)bh * ND * NT;
    const float* Vg = g_v  + (size_t)bh * NT * ND;

    {
        const int r = tid;
#pragma unroll
        for (int d4 = 0; d4 < 16; d4++) {
            float4 v = *(const float4*)(Qg + (size_t)r * ND + d4 * 4);
            Qst[(d4 * 4 + 0) * 128 + r] = v.x * SCALE;
            Qst[(d4 * 4 + 1) * 128 + r] = v.y * SCALE;
            Qst[(d4 * 4 + 2) * 128 + r] = v.z * SCALE;
            Qst[(d4 * 4 + 3) * 128 + r] = v.w * SCALE;
        }
    }

    float m_i[8], l_i[8], o[8][8];
#pragma unroll
    for (int i = 0; i < 8; i++) {
        m_i[i] = -1e30f;
        l_i[i] = 0.0f;
#pragma unroll
        for (int j = 0; j < 8; j++) o[i][j] = 0.0f;
    }

    const int nkt = 2 * qt + 2;
    for (int jt = 0; jt < nkt; jt++) {
        const int k0 = jt * 64;
        __syncthreads();

#pragma unroll
        for (int p = 0; p < 8; p++) {
            const int lin = p * 512 + tid * 4;
            const int d = lin >> 6, kq = lin & 63;
            float4 kv = *(const float4*)(Kg + (size_t)d * NT + k0 + kq);
            *(float4*)&Kst[d * 64 + kq] = kv;
            float4 vv = *(const float4*)(Vg + (size_t)k0 * ND + lin);
            *(float4*)&Vs[lin] = vv;
        }
        __syncthreads();

        float s[8][8];
#pragma unroll
        for (int i = 0; i < 8; i++)
#pragma unroll
            for (int j = 0; j < 8; j++) s[i][j] = 0.0f;

#pragma unroll 8
        for (int kk = 0; kk < 64; kk++) {
            float4 qa = *(const float4*)&Qst[kk * 128 + ty * 4];
            float4 qb = *(const float4*)&Qst[kk * 128 + 64 + ty * 4];
            float4 ka = *(const float4*)&Kst[kk * 64 + tx * 4];
            float4 kb = *(const float4*)&Kst[kk * 64 + 32 + tx * 4];
            float a[8] = {qa.x, qa.y, qa.z, qa.w, qb.x, qb.y, qb.z, qb.w};
            float b[8] = {ka.x, ka.y, ka.z, ka.w, kb.x, kb.y, kb.z, kb.w};
#pragma unroll
            for (int i = 0; i < 8; i++)
#pragma unroll
                for (int j = 0; j < 8; j++)
                    s[i][j] += a[i] * b[j];
        }

        if (jt >= 2 * qt) {
#pragma unroll
            for (int i = 0; i < 8; i++) {
                const int q = q0 + ((i < 4) ? (ty * 4 + i) : (64 + ty * 4 + i - 4));
#pragma unroll
                for (int j = 0; j < 8; j++) {
                    const int kc = k0 + ((j < 4) ? (tx * 4 + j) : (32 + tx * 4 + j - 4));
                    if (kc > q) s[i][j] = -1e30f;
                }
            }
        }

#pragma unroll
        for (int i = 0; i < 8; i++) {
            float mx = s[i][0];
#pragma unroll
            for (int j = 1; j < 8; j++) mx = fmaxf(mx, s[i][j]);
            mx = fmaxf(mx, __shfl_xor_sync(0xffffffffu, mx, 1));
            mx = fmaxf(mx, __shfl_xor_sync(0xffffffffu, mx, 2));
            mx = fmaxf(mx, __shfl_xor_sync(0xffffffffu, mx, 4));
            const float mnew = fmaxf(m_i[i], mx);
            const float fac  = exp2f(m_i[i] - mnew);
            float rs = 0.0f;
#pragma unroll
            for (int j = 0; j < 8; j++) {
                s[i][j] = exp2f(s[i][j] - mnew);
                rs += s[i][j];
            }
            rs += __shfl_xor_sync(0xffffffffu, rs, 1);
            rs += __shfl_xor_sync(0xffffffffu, rs, 2);
            rs += __shfl_xor_sync(0xffffffffu, rs, 4);
            l_i[i] = l_i[i] * fac + rs;
            m_i[i] = mnew;
#pragma unroll
            for (int j = 0; j < 8; j++) o[i][j] *= fac;
        }

#pragma unroll
        for (int j = 0; j < 8; j++) {
            const int col = (j < 4) ? (tx * 4 + j) : (32 + tx * 4 + (j - 4));
            float4 v0 = make_float4(s[0][j], s[1][j], s[2][j], s[3][j]);
            float4 v1 = make_float4(s[4][j], s[5][j], s[6][j], s[7][j]);
            *(float4*)&Pst[col * 132 + ty * 4]      = v0;
            *(float4*)&Pst[col * 132 + 64 + ty * 4] = v1;
        }
        __syncthreads();

#pragma unroll 8
        for (int kk = 0; kk < 64; kk++) {
            float4 pa = *(const float4*)&Pst[kk * 132 + ty * 4];
            float4 pb = *(const float4*)&Pst[kk * 132 + 64 + ty * 4];
            float4 va = *(const float4*)&Vs[kk * 64 + tx * 4];
            float4 vb = *(const float4*)&Vs[kk * 64 + 32 + tx * 4];
            float p[8] = {pa.x, pa.y, pa.z, pa.w, pb.x, pb.y, pb.z, pb.w};
            float v[8] = {va.x, va.y, va.z, va.w, vb.x, vb.y, vb.z, vb.w};
#pragma unroll
            for (int i = 0; i < 8; i++)
#pragma unroll
                for (int j = 0; j < 8; j++)
                    o[i][j] += p[i] * v[j];
        }
    }

    const int b = bh >> 4;
    const int h = bh & 15;
#pragma unroll
    for (int i = 0; i < 8; i++) {
        const int q = q0 + ((i < 4) ? (ty * 4 + i) : (64 + ty * 4 + (i - 4)));
        const float inv = 1.0f / l_i[i];
        float4 r0 = make_float4(o[i][0] * inv, o[i][1] * inv, o[i][2] * inv, o[i][3] * inv);
        float4 r1 = make_float4(o[i][4] * inv, o[i][5] * inv, o[i][6] * inv, o[i][7] * inv);
        const size_t base = ((size_t)(b * NT + q)) * NC + h * ND;
        *(float4*)&g_att[base + tx * 4]      = r0;
        *(float4*)&g_att[base + 32 + tx * 4] = r1;
    }
}

// ---------------------------------------------------------------------------
// kernel_launch
// ---------------------------------------------------------------------------
extern "C" void kernel_launch(void* const* d_in, const int* in_sizes, int n_in,
                              void* d_out, int out_size)
{
    const float* x     = (const float*)d_in[0];
    const float* w_qkv = (const float*)d_in[1];
    const float* b_qkv = (const float*)d_in[2];
    const float* w_out = (const float*)d_in[3];
    const float* b_out = (const float*)d_in[4];
    float* out = (float*)d_out;

    cudaFuncSetAttribute((const void*)flash_kernel,
                         cudaFuncAttributeMaxDynamicSharedMemorySize, FLASH_SMEM_BYTES);
    cudaFuncSetAttribute((const void*)gemm_mma<NQKV, 1>,
                         cudaFuncAttributeMaxDynamicSharedMemorySize, GEMM_SMEM);
    cudaFuncSetAttribute((const void*)gemm_mma<NC, 0>,
                         cudaFuncAttributeMaxDynamicSharedMemorySize, GEMM_SMEM);

    void *p_ah, *p_al, *p_wqh, *p_wql, *p_woh, *p_wol, *p_att, *p_atth, *p_attl;
    cudaGetSymbolAddress(&p_ah,   g_ah);
    cudaGetSymbolAddress(&p_al,   g_al);
    cudaGetSymbolAddress(&p_wqh,  g_wqT_h);
    cudaGetSymbolAddress(&p_wql,  g_wqT_l);
    cudaGetSymbolAddress(&p_woh,  g_woT_h);
    cudaGetSymbolAddress(&p_wol,  g_woT_l);
    cudaGetSymbolAddress(&p_att,  g_att);
    cudaGetSymbolAddress(&p_atth, g_atth);
    cudaGetSymbolAddress(&p_attl, g_attl);

    const int n4 = NM * NC / 4;

    // 1) Split inputs to bf16 hi/lo
    convert_split_kernel<<<(n4 + 255) / 256, 256>>>(
        x, (__nv_bfloat16*)p_ah, (__nv_bfloat16*)p_al, n4);
    transpose_split_kernel<<<dim3(NQKV / 32, NC / 32), dim3(32, 8)>>>(
        w_qkv, (__nv_bfloat16*)p_wqh, (__nv_bfloat16*)p_wql, NC, NQKV);
    transpose_split_kernel<<<dim3(NC / 32, NC / 32), dim3(32, 8)>>>(
        w_out, (__nv_bfloat16*)p_woh, (__nv_bfloat16*)p_wol, NC, NC);

    // 2) QKV projection (tensor-core bf16 split-3) + scatter to q / kT / v
    gemm_mma<NQKV, 1><<<dim3(NQKV / 128, NM / 128), 256, GEMM_SMEM>>>(
        (const __nv_bfloat16*)p_ah, (const __nv_bfloat16*)p_al,
        (const __nv_bfloat16*)p_wqh, (const __nv_bfloat16*)p_wql,
        b_qkv, nullptr);

    // 3) Causal flash attention (fp32) -> g_att
    flash_kernel<<<dim3(NT / 128, NB * NH), 128, FLASH_SMEM_BYTES>>>();

    // 4) Split attention output, then output projection (tensor-core bf16 split-3)
    convert_split_kernel<<<(n4 + 255) / 256, 256>>>(
        (const float*)p_att, (__nv_bfloat16*)p_atth, (__nv_bfloat16*)p_attl, n4);
    gemm_mma<NC, 0><<<dim3(NC / 128, NM / 128), 256, GEMM_SMEM>>>(
        (const __nv_bfloat16*)p_atth, (const __nv_bfloat16*)p_attl,
        (const __nv_bfloat16*)p_woh, (const __nv_bfloat16*)p_wol,
        b_out, out);
}

// round 11
// speedup vs baseline: 2.1125x; 1.5412x over previous
#include <cuda_runtime.h>
#include <cuda_bf16.h>
#include <stdint.h>
#include <math.h>

// Problem constants
#define NB 4
#define NT 2048
#define NC 1024
#define NH 16
#define ND 64
#define NM (NB * NT)      // 8192
#define NQKV (3 * NC)     // 3072

#define QSCALE (0.125f * 1.44269504088896340736f)   // 1/sqrt(64) * log2(e)

// ---------------------------------------------------------------------------
// Scratch (device globals — no runtime allocation allowed)
// ---------------------------------------------------------------------------
// bf16 split operands for the dense GEMMs
__device__ __nv_bfloat16 g_ah   [(size_t)NM * NC];
__device__ __nv_bfloat16 g_al   [(size_t)NM * NC];
__device__ __nv_bfloat16 g_wqT_h[(size_t)NQKV * NC];   // w_qkv^T  [N][K]
__device__ __nv_bfloat16 g_wqT_l[(size_t)NQKV * NC];
__device__ __nv_bfloat16 g_woT_h[(size_t)NC * NC];     // w_out^T  [N][K]
__device__ __nv_bfloat16 g_woT_l[(size_t)NC * NC];
__device__ __nv_bfloat16 g_atth [(size_t)NM * NC];     // flash out hi [B,T,C]
__device__ __nv_bfloat16 g_attl [(size_t)NM * NC];     // flash out lo

// flash operands, pre-split bf16 (written by QKV epilogue)
__device__ __nv_bfloat16 g_qh [(size_t)NB * NH * NT * ND];  // [bh][t][d] (scaled)
__device__ __nv_bfloat16 g_ql [(size_t)NB * NH * NT * ND];
__device__ __nv_bfloat16 g_kh [(size_t)NB * NH * NT * ND];  // [bh][t][d]
__device__ __nv_bfloat16 g_kl [(size_t)NB * NH * NT * ND];
__device__ __nv_bfloat16 g_vTh[(size_t)NB * NH * ND * NT];  // [bh][d][t]
__device__ __nv_bfloat16 g_vTl[(size_t)NB * NH * ND * NT];

// ---------------------------------------------------------------------------
// PTX helpers (sm_80-class: ldmatrix / mma.sync / cp.async — base sm_103 legal)
// ---------------------------------------------------------------------------
__device__ __forceinline__ uint32_t smem_u32(const void* p) {
    uint32_t a;
    asm("{ .reg .u64 t; cvta.to.shared.u64 t, %1; cvt.u32.u64 %0, t; }"
        : "=r"(a) : "l"(p));
    return a;
}

__device__ __forceinline__ void ldm_x4(uint32_t* r, uint32_t addr) {
    asm volatile("ldmatrix.sync.aligned.m8n8.x4.shared.b16 {%0,%1,%2,%3}, [%4];"
                 : "=r"(r[0]), "=r"(r[1]), "=r"(r[2]), "=r"(r[3]) : "r"(addr));
}

__device__ __forceinline__ void mma_bf16(float* c, const uint32_t* a,
                                         uint32_t b0, uint32_t b1) {
    asm volatile(
        "mma.sync.aligned.m16n8k16.row.col.f32.bf16.bf16.f32 "
        "{%0,%1,%2,%3}, {%4,%5,%6,%7}, {%8,%9}, {%0,%1,%2,%3};"
        : "+f"(c[0]), "+f"(c[1]), "+f"(c[2]), "+f"(c[3])
        : "r"(a[0]), "r"(a[1]), "r"(a[2]), "r"(a[3]), "r"(b0), "r"(b1));
}

#define CP_ASYNC16(dst, src) \
    asm volatile("cp.async.cg.shared.global [%0], [%1], 16;" \
                 :: "r"(dst), "l"(src) : "memory")
#define CP_COMMIT()  asm volatile("cp.async.commit_group;" ::: "memory")
#define CP_WAIT(n)   asm volatile("cp.async.wait_group %0;" :: "n"(n) : "memory")

#define SW128(o) ((o) ^ (((o) >> 3) & 0x70))

// fp32 pair -> bf16x2 hi word + bf16x2 residual word
__device__ __forceinline__ void pack_split(float x, float y,
                                           uint32_t& hi, uint32_t& lo) {
    __nv_bfloat16 hx = __float2bfloat16(x);
    __nv_bfloat16 hy = __float2bfloat16(y);
    __nv_bfloat162 h2(hx, hy);
    hi = *(uint32_t*)&h2;
    __nv_bfloat162 l2(__float2bfloat16(x - __bfloat162float(hx)),
                      __float2bfloat16(y - __bfloat162float(hy)));
    lo = *(uint32_t*)&l2;
}

// ---------------------------------------------------------------------------
// Conversion kernels (fp32 -> bf16 hi/lo split)
// ---------------------------------------------------------------------------
__global__ void convert_split_kernel(const float* __restrict__ in,
                                     __nv_bfloat16* __restrict__ hi,
                                     __nv_bfloat16* __restrict__ lo, int n4)
{
    int i = blockIdx.x * blockDim.x + threadIdx.x;
    if (i >= n4) return;
    float4 v = ((const float4*)in)[i];
    uint32_t h0, l0, h1, l1;
    pack_split(v.x, v.y, h0, l0);
    pack_split(v.z, v.w, h1, l1);
    ((uint32_t*)hi)[2 * i]     = h0;
    ((uint32_t*)hi)[2 * i + 1] = h1;
    ((uint32_t*)lo)[2 * i]     = l0;
    ((uint32_t*)lo)[2 * i + 1] = l1;
}

// W [K][N] fp32  ->  Th/Tl [N][K] bf16 (transpose + split)
__global__ void transpose_split_kernel(const float* __restrict__ W,
                                       __nv_bfloat16* __restrict__ Th,
                                       __nv_bfloat16* __restrict__ Tl,
                                       int Kdim, int Ndim)
{
    __shared__ float tile[32][33];
    const int nx = blockIdx.x * 32 + threadIdx.x;
    const int ky = blockIdx.y * 32;
#pragma unroll
    for (int i = threadIdx.y; i < 32; i += 8)
        tile[i][threadIdx.x] = W[(size_t)(ky + i) * Ndim + nx];
    __syncthreads();
    const int k = ky + threadIdx.x;
#pragma unroll
    for (int i = threadIdx.y; i < 32; i += 8) {
        const int n = blockIdx.x * 32 + i;
        const float v = tile[threadIdx.x][i];
        __nv_bfloat16 h = __float2bfloat16(v);
        Th[(size_t)n * Kdim + k] = h;
        Tl[(size_t)n * Kdim + k] = __float2bfloat16(v - __bfloat162float(h));
    }
}

// ---------------------------------------------------------------------------
// mma.sync bf16-split3 GEMM: C[M,NTOT] = A[M,1024] @ B^T + bias
//   C = Ah*Bh + Ah*Bl + Al*Bh  (fp32 accumulate)
// CTA 128x128, BK=32, 256 threads (8 warps 4x2, warp tile 32x64),
// cp.async 4-stage pipeline, 80B padded smem rows.
// MODE 0: fp32 out + bias.  MODE 1: QKV scatter -> pre-split flash operands.
// ---------------------------------------------------------------------------
#define TILE_B   10240               // 128 rows * 80 B
#define STAGE_B  (4 * TILE_B)        // Ah, Al, Bh, Bl
#define GEMM_SMEM (4 * STAGE_B)      // 163840 B (4 stages)

template <int NTOT, int MODE>
__global__ __launch_bounds__(256, 1)
void gemm_mma(const __nv_bfloat16* __restrict__ Ahg, const __nv_bfloat16* __restrict__ Alg,
              const __nv_bfloat16* __restrict__ Bhg, const __nv_bfloat16* __restrict__ Blg,
              const float* __restrict__ bias, float* __restrict__ out)
{
    extern __shared__ char smem[];
    const uint32_t sb = smem_u32(smem);
    const int tid = threadIdx.x;
    const int wid = tid >> 5, lane = tid & 31;
    const int wm = wid & 3, wn = wid >> 2;
    const int bn = blockIdx.x, bm = blockIdx.y;

    const __nv_bfloat16* srcs[4] = {Ahg, Alg, Bhg, Blg};

    float acc[2][8][4];
#pragma unroll
    for (int i = 0; i < 2; i++)
#pragma unroll
        for (int j = 0; j < 8; j++)
#pragma unroll
            for (int f = 0; f < 4; f++) acc[i][j][f] = 0.0f;

    const int r_ld[2]  = {tid >> 2, (tid + 256) >> 2};
    const int c_ld     = (tid & 3) * 16;   // byte col within 64B row

    auto issue_loads = [&](int kc, int st) {
#pragma unroll
        for (int t4 = 0; t4 < 4; t4++) {
            const size_t rb = (t4 < 2) ? (size_t)bm * 128 : (size_t)bn * 128;
            const __nv_bfloat16* src = srcs[t4] + rb * NC + kc * 32;
            const uint32_t dst = sb + st * STAGE_B + t4 * TILE_B;
#pragma unroll
            for (int u = 0; u < 2; u++) {
                const int r = r_ld[u];
                CP_ASYNC16(dst + r * 80 + c_ld,
                           (const char*)(src + (size_t)r * NC) + c_ld);
            }
        }
        CP_COMMIT();
    };

    issue_loads(0, 0);
    issue_loads(1, 1);
    issue_loads(2, 2);

    for (int kc = 0; kc < 32; kc++) {
        const int st = kc & 3;
        if (kc < 30)       CP_WAIT(2);
        else if (kc == 30) CP_WAIT(1);
        else               CP_WAIT(0);
        __syncthreads();

        const uint32_t stb = sb + st * STAGE_B;
        const uint32_t lrow = (lane & 15);
        const uint32_t lcol = (lane >> 4) * 16;

#pragma unroll
        for (int k16 = 0; k16 < 2; k16++) {
            const uint32_t koff = k16 * 32 + lcol;
            uint32_t aH[2][4], aL[2][4], bH[4][4], bL[4][4];
#pragma unroll
            for (int i = 0; i < 2; i++) {
                const uint32_t row = wm * 32 + i * 16 + lrow;
                ldm_x4(aH[i], stb + 0 * TILE_B + row * 80 + koff);
                ldm_x4(aL[i], stb + 1 * TILE_B + row * 80 + koff);
            }
#pragma unroll
            for (int j2 = 0; j2 < 4; j2++) {
                const uint32_t row = wn * 64 + j2 * 16 + lrow;
                ldm_x4(bH[j2], stb + 2 * TILE_B + row * 80 + koff);
                ldm_x4(bL[j2], stb + 3 * TILE_B + row * 80 + koff);
            }
#pragma unroll
            for (int i = 0; i < 2; i++)
#pragma unroll
                for (int j = 0; j < 8; j++) {
                    const int j2 = j >> 1, o = j & 1;
                    mma_bf16(acc[i][j], aH[i], bH[j2][o], bH[j2][o + 2]);
                    mma_bf16(acc[i][j], aH[i], bL[j2][o], bL[j2][o + 2]);
                    mma_bf16(acc[i][j], aL[i], bH[j2][o], bH[j2][o + 2]);
                }
        }
        __syncthreads();
        if (kc + 3 < 32) issue_loads(kc + 3, (kc + 3) & 3);
    }

    // Epilogue
    const int rr = lane >> 2;
    const int cc = (lane & 3) * 2;
#pragma unroll
    for (int i = 0; i < 2; i++) {
#pragma unroll
        for (int j = 0; j < 8; j++) {
            const int gc = bn * 128 + wn * 64 + j * 8 + cc;
            const float bz0 = bias[gc], bz1 = bias[gc + 1];
#pragma unroll
            for (int h2 = 0; h2 < 2; h2++) {
                const int gm = bm * 128 + wm * 32 + i * 16 + h2 * 8 + rr;
                const float v0 = acc[i][j][h2 * 2 + 0] + bz0;
                const float v1 = acc[i][j][h2 * 2 + 1] + bz1;
                if (MODE == 0) {
                    *(float2*)&out[(size_t)gm * NTOT + gc] = make_float2(v0, v1);
                } else {
                    const int part = gc >> 10;          // 0=q 1=k 2=v
                    const int h  = (gc & (NC - 1)) >> 6;
                    const int d0 = gc & 63;
                    const int b  = gm >> 11;
                    const int tt = gm & (NT - 1);
                    const int bh = b * NH + h;
                    if (part == 0) {
                        uint32_t hi, lo;
                        pack_split(v0 * QSCALE, v1 * QSCALE, hi, lo);
                        const size_t base = ((size_t)bh * NT + tt) * ND + d0;
                        *(uint32_t*)&g_qh[base] = hi;
                        *(uint32_t*)&g_ql[base] = lo;
                    } else if (part == 1) {
                        uint32_t hi, lo;
                        pack_split(v0, v1, hi, lo);
                        const size_t base = ((size_t)bh * NT + tt) * ND + d0;
                        *(uint32_t*)&g_kh[base] = hi;
                        *(uint32_t*)&g_kl[base] = lo;
                    } else {
                        const size_t base = ((size_t)bh * ND + d0) * NT + tt;
                        __nv_bfloat16 h0 = __float2bfloat16(v0);
                        __nv_bfloat16 h1 = __float2bfloat16(v1);
                        g_vTh[base]      = h0;
                        g_vTh[base + NT] = h1;
                        g_vTl[base]      = __float2bfloat16(v0 - __bfloat162float(h0));
                        g_vTl[base + NT] = __float2bfloat16(v1 - __bfloat162float(h1));
                    }
                }
            }
        }
    }
}

// ---------------------------------------------------------------------------
// Flash attention v2 (tensor-core, bf16 split-3 for S and PV, fp32 softmax)
// CTA: 128 q-rows x one bh. 256 threads = 8 warps, warp = 16 q-rows.
// K-tiles of 64 keys, double-buffered cp.async.
// Smem: Qh/Ql [128][64], per-stage Kh/Kl [64][64] + VTh/VTl [64][64] (SW128).
// ---------------------------------------------------------------------------
#define FL2_SMEM (32768 + 2 * 32768)   // 98304 B

__global__ __launch_bounds__(256, 1)
void flash2_kernel()
{
    extern __shared__ char smc[];
    const uint32_t sb = smem_u32(smc);
    const int tid = threadIdx.x;
    const int w = tid >> 5, lane = tid & 31;
    const int qt = blockIdx.x, bh = blockIdx.y;
    const int q0 = qt * 128;

    const __nv_bfloat16* Qh_g = g_qh + ((size_t)bh * NT + q0) * ND;
    const __nv_bfloat16* Ql_g = g_ql + ((size_t)bh * NT + q0) * ND;
    const __nv_bfloat16* Kh_g = g_kh + (size_t)bh * NT * ND;
    const __nv_bfloat16* Kl_g = g_kl + (size_t)bh * NT * ND;
    const __nv_bfloat16* Vh_g = g_vTh + (size_t)bh * ND * NT;
    const __nv_bfloat16* Vl_g = g_vTl + (size_t)bh * ND * NT;

    const uint32_t sQh = sb, sQl = sb + 16384;

    auto load_kv = [&](int jt, int st) {
        const int k0 = jt * 64;
        const uint32_t base = sb + 32768 + st * 32768;
#pragma unroll
        for (int u = 0; u < 2; u++) {
            const int idx = tid + u * 256;            // 0..511
            const int r = idx >> 3, c = (idx & 7) * 16;
            const uint32_t sw = SW128(r * 128 + c);
            CP_ASYNC16(base +         sw, (const char*)(Kh_g + (size_t)(k0 + r) * ND) + c);
            CP_ASYNC16(base +  8192 + sw, (const char*)(Kl_g + (size_t)(k0 + r) * ND) + c);
            CP_ASYNC16(base + 16384 + sw, (const char*)(Vh_g + (size_t)r * NT + k0) + c);
            CP_ASYNC16(base + 24576 + sw, (const char*)(Vl_g + (size_t)r * NT + k0) + c);
        }
        CP_COMMIT();
    };

    // Q tile load (with group 0)
#pragma unroll
    for (int u = 0; u < 4; u++) {
        const int idx = tid + u * 256;                // 0..1023
        const int r = idx >> 3, c = (idx & 7) * 16;
        const uint32_t sw = SW128(r * 128 + c);
        CP_ASYNC16(sQh + sw, (const char*)(Qh_g + (size_t)r * ND) + c);
        CP_ASYNC16(sQl + sw, (const char*)(Ql_g + (size_t)r * ND) + c);
    }
    load_kv(0, 0);
    load_kv(1, 1);

    const int nkt = 2 * qt + 2;
    const uint32_t lrow = lane & 15, lcolB = (lane >> 4) * 16;

    uint32_t qfh[4][4], qfl[4][4];
    float m0 = -1e30f, m1 = -1e30f, l0 = 0.0f, l1 = 0.0f;
    float o[8][4];
#pragma unroll
    for (int j = 0; j < 8; j++)
#pragma unroll
        for (int f = 0; f < 4; f++) o[j][f] = 0.0f;

    for (int jt = 0; jt < nkt; jt++) {
        const int st = jt & 1;
        if (jt + 1 < nkt) CP_WAIT(1); else CP_WAIT(0);
        __syncthreads();

        if (jt == 0) {
#pragma unroll
            for (int kt = 0; kt < 4; kt++) {
                const uint32_t off = SW128((w * 16 + lrow) * 128 + kt * 32 + lcolB);
                ldm_x4(qfh[kt], sQh + off);
                ldm_x4(qfl[kt], sQl + off);
            }
        }

        const bool diag0 = (jt == 2 * qt);
        const bool diag1 = (jt == 2 * qt + 1);
        const bool skip  = diag1 && (w < 4);    // fully masked sub-tile

        if (!skip) {
            const uint32_t kb = sb + 32768 + st * 32768;

            // S = Q K^T (split-3)
            float s[8][4];
#pragma unroll
            for (int j = 0; j < 8; j++)
#pragma unroll
                for (int f = 0; f < 4; f++) s[j][f] = 0.0f;

#pragma unroll
            for (int kt = 0; kt < 4; kt++) {
                uint32_t bKh[4][4], bKl[4][4];
#pragma unroll
                for (int j2 = 0; j2 < 4; j2++) {
                    const uint32_t off = SW128((j2 * 16 + lrow) * 128 + kt * 32 + lcolB);
                    ldm_x4(bKh[j2], kb + off);
                    ldm_x4(bKl[j2], kb + 8192 + off);
                }
#pragma unroll
                for (int j = 0; j < 8; j++) {
                    const int j2 = j >> 1, od = j & 1;
                    mma_bf16(s[j], qfh[kt], bKh[j2][od], bKh[j2][od + 2]);
                    mma_bf16(s[j], qfh[kt], bKl[j2][od], bKl[j2][od + 2]);
                    mma_bf16(s[j], qfl[kt], bKh[j2][od], bKh[j2][od + 2]);
                }
            }

            // causal mask on diagonal sub-tiles
            if ((diag0 && w < 4) || diag1) {
                const int qloc  = w * 16 + (lane >> 2);
                const int kbase = diag1 ? 64 : 0;
#pragma unroll
                for (int j = 0; j < 8; j++) {
                    const int kc = kbase + j * 8 + (lane & 3) * 2;
                    if (kc     > qloc)     s[j][0] = -1e30f;
                    if (kc + 1 > qloc)     s[j][1] = -1e30f;
                    if (kc     > qloc + 8) s[j][2] = -1e30f;
                    if (kc + 1 > qloc + 8) s[j][3] = -1e30f;
                }
            }

            // online softmax (exp2 domain; rows r=lane>>2 and r+8)
            float mx0 = -1e30f, mx1 = -1e30f;
#pragma unroll
            for (int j = 0; j < 8; j++) {
                mx0 = fmaxf(mx0, fmaxf(s[j][0], s[j][1]));
                mx1 = fmaxf(mx1, fmaxf(s[j][2], s[j][3]));
            }
            mx0 = fmaxf(mx0, __shfl_xor_sync(0xffffffffu, mx0, 1));
            mx0 = fmaxf(mx0, __shfl_xor_sync(0xffffffffu, mx0, 2));
            mx1 = fmaxf(mx1, __shfl_xor_sync(0xffffffffu, mx1, 1));
            mx1 = fmaxf(mx1, __shfl_xor_sync(0xffffffffu, mx1, 2));
            const float mn0 = fmaxf(m0, mx0), mn1 = fmaxf(m1, mx1);
            const float f0 = exp2f(m0 - mn0), f1 = exp2f(m1 - mn1);
            float rs0 = 0.0f, rs1 = 0.0f;
#pragma unroll
            for (int j = 0; j < 8; j++) {
                s[j][0] = exp2f(s[j][0] - mn0);
                s[j][1] = exp2f(s[j][1] - mn0);
                s[j][2] = exp2f(s[j][2] - mn1);
                s[j][3] = exp2f(s[j][3] - mn1);
                rs0 += s[j][0] + s[j][1];
                rs1 += s[j][2] + s[j][3];
            }
            rs0 += __shfl_xor_sync(0xffffffffu, rs0, 1);
            rs0 += __shfl_xor_sync(0xffffffffu, rs0, 2);
            rs1 += __shfl_xor_sync(0xffffffffu, rs1, 1);
            rs1 += __shfl_xor_sync(0xffffffffu, rs1, 2);
            l0 = l0 * f0 + rs0; m0 = mn0;
            l1 = l1 * f1 + rs1; m1 = mn1;
#pragma unroll
            for (int j = 0; j < 8; j++) {
                o[j][0] *= f0; o[j][1] *= f0;
                o[j][2] *= f1; o[j][3] *= f1;
            }

            // repack P (C-frag -> A-frag), split hi/lo
            uint32_t ph[4][4], pl[4][4];
#pragma unroll
            for (int kt = 0; kt < 4; kt++) {
                pack_split(s[2 * kt][0],     s[2 * kt][1],     ph[kt][0], pl[kt][0]);
                pack_split(s[2 * kt][2],     s[2 * kt][3],     ph[kt][1], pl[kt][1]);
                pack_split(s[2 * kt + 1][0], s[2 * kt + 1][1], ph[kt][2], pl[kt][2]);
                pack_split(s[2 * kt + 1][2], s[2 * kt + 1][3], ph[kt][3], pl[kt][3]);
            }

            // O += P V (split-3), B = V^T smem [d][key]
            const uint32_t vb = kb + 16384;
#pragma unroll
            for (int kt = 0; kt < 4; kt++) {
                uint32_t bVh[4][4], bVl[4][4];
#pragma unroll
                for (int j2 = 0; j2 < 4; j2++) {
                    const uint32_t off = SW128((j2 * 16 + lrow) * 128 + kt * 32 + lcolB);
                    ldm_x4(bVh[j2], vb + off);
                    ldm_x4(bVl[j2], vb + 8192 + off);
                }
#pragma unroll
                for (int j = 0; j < 8; j++) {
                    const int j2 = j >> 1, od = j & 1;
                    mma_bf16(o[j], ph[kt], bVh[j2][od], bVh[j2][od + 2]);
                    mma_bf16(o[j], ph[kt], bVl[j2][od], bVl[j2][od + 2]);
                    mma_bf16(o[j], pl[kt], bVh[j2][od], bVh[j2][od + 2]);
                }
            }
        }

        __syncthreads();
        if (jt + 2 < nkt) load_kv(jt + 2, st);
    }

    // Epilogue: normalize, split, write g_atth/g_attl [B,T,C]
    const int b = bh >> 4, h = bh & 15;
    const int r0g = q0 + w * 16 + (lane >> 2);
    const float inv0 = 1.0f / l0, inv1 = 1.0f / l1;
#pragma unroll
    for (int j = 0; j < 8; j++) {
        const int dc = j * 8 + (lane & 3) * 2;
        const size_t base = ((size_t)(b * NT + r0g)) * NC + h * 64 + dc;
        uint32_t hi, lo;
        pack_split(o[j][0] * inv0, o[j][1] * inv0, hi, lo);
        *(uint32_t*)&g_atth[base] = hi;
        *(uint32_t*)&g_attl[base] = lo;
        pack_split(o[j][2] * inv1, o[j][3] * inv1, hi, lo);
        *(uint32_t*)&g_atth[base + 8 * NC] = hi;
        *(uint32_t*)&g_attl[base + 8 * NC] = lo;
    }
}

// ---------------------------------------------------------------------------
// kernel_launch
// ---------------------------------------------------------------------------
extern "C" void kernel_launch(void* const* d_in, const int* in_sizes, int n_in,
                              void* d_out, int out_size)
{
    const float* x     = (const float*)d_in[0];
    const float* w_qkv = (const float*)d_in[1];
    const float* b_qkv = (const float*)d_in[2];
    const float* w_out = (const float*)d_in[3];
    const float* b_out = (const float*)d_in[4];
    float* out = (float*)d_out;

    cudaFuncSetAttribute((const void*)flash2_kernel,
                         cudaFuncAttributeMaxDynamicSharedMemorySize, FL2_SMEM);
    cudaFuncSetAttribute((const void*)gemm_mma<NQKV, 1>,
                         cudaFuncAttributeMaxDynamicSharedMemorySize, GEMM_SMEM);
    cudaFuncSetAttribute((const void*)gemm_mma<NC, 0>,
                         cudaFuncAttributeMaxDynamicSharedMemorySize, GEMM_SMEM);

    void *p_ah, *p_al, *p_wqh, *p_wql, *p_woh, *p_wol, *p_atth, *p_attl;
    cudaGetSymbolAddress(&p_ah,   g_ah);
    cudaGetSymbolAddress(&p_al,   g_al);
    cudaGetSymbolAddress(&p_wqh,  g_wqT_h);
    cudaGetSymbolAddress(&p_wql,  g_wqT_l);
    cudaGetSymbolAddress(&p_woh,  g_woT_h);
    cudaGetSymbolAddress(&p_wol,  g_woT_l);
    cudaGetSymbolAddress(&p_atth, g_atth);
    cudaGetSymbolAddress(&p_attl, g_attl);

    const int n4 = NM * NC / 4;

    // 1) Split x, transpose+split weights
    convert_split_kernel<<<(n4 + 255) / 256, 256>>>(
        x, (__nv_bfloat16*)p_ah, (__nv_bfloat16*)p_al, n4);
    transpose_split_kernel<<<dim3(NQKV / 32, NC / 32), dim3(32, 8)>>>(
        w_qkv, (__nv_bfloat16*)p_wqh, (__nv_bfloat16*)p_wql, NC, NQKV);
    transpose_split_kernel<<<dim3(NC / 32, NC / 32), dim3(32, 8)>>>(
        w_out, (__nv_bfloat16*)p_woh, (__nv_bfloat16*)p_wol, NC, NC);

    // 2) QKV projection -> pre-split bf16 flash operands
    gemm_mma<NQKV, 1><<<dim3(NQKV / 128, NM / 128), 256, GEMM_SMEM>>>(
        (const __nv_bfloat16*)p_ah, (const __nv_bfloat16*)p_al,
        (const __nv_bfloat16*)p_wqh, (const __nv_bfloat16*)p_wql,
        b_qkv, nullptr);

    // 3) Tensor-core causal flash attention -> g_atth/g_attl
    flash2_kernel<<<dim3(NT / 128, NB * NH), 256, FL2_SMEM>>>();

    // 4) Output projection
    gemm_mma<NC, 0><<<dim3(NC / 128, NM / 128), 256, GEMM_SMEM>>>(
        (const __nv_bfloat16*)p_atth, (const __nv_bfloat16*)p_attl,
        (const __nv_bfloat16*)p_woh, (const __nv_bfloat16*)p_wol,
        b_out, out);
}

// round 12
// speedup vs baseline: 2.3342x; 1.1050x over previous
#include <cuda_runtime.h>
#include <cuda_bf16.h>
#include <stdint.h>
#include <math.h>

// Problem constants
#define NB 4
#define NT 2048
#define NC 1024
#define NH 16
#define ND 64
#define NM (NB * NT)      // 8192
#define NQKV (3 * NC)     // 3072

#define QSCALE (0.125f * 1.44269504088896340736f)   // 1/sqrt(64) * log2(e)

// ---------------------------------------------------------------------------
// Scratch (device globals — no runtime allocation allowed)
// ---------------------------------------------------------------------------
__device__ __nv_bfloat16 g_ah   [(size_t)NM * NC];
__device__ __nv_bfloat16 g_al   [(size_t)NM * NC];
__device__ __nv_bfloat16 g_wqT_h[(size_t)NQKV * NC];   // w_qkv^T  [N][K]
__device__ __nv_bfloat16 g_wqT_l[(size_t)NQKV * NC];
__device__ __nv_bfloat16 g_woT_h[(size_t)NC * NC];     // w_out^T  [N][K]
__device__ __nv_bfloat16 g_woT_l[(size_t)NC * NC];
__device__ __nv_bfloat16 g_atth [(size_t)NM * NC];     // flash out hi [B,T,C]
__device__ __nv_bfloat16 g_attl [(size_t)NM * NC];     // flash out lo

// flash operands, pre-split bf16 (written by QKV epilogue)
__device__ __nv_bfloat16 g_qh [(size_t)NB * NH * NT * ND];  // [bh][t][d] (scaled)
__device__ __nv_bfloat16 g_ql [(size_t)NB * NH * NT * ND];
__device__ __nv_bfloat16 g_kh [(size_t)NB * NH * NT * ND];  // [bh][t][d]
__device__ __nv_bfloat16 g_kl [(size_t)NB * NH * NT * ND];
__device__ __nv_bfloat16 g_vTh[(size_t)NB * NH * ND * NT];  // [bh][d][t]
__device__ __nv_bfloat16 g_vTl[(size_t)NB * NH * ND * NT];

// ---------------------------------------------------------------------------
// PTX helpers (sm_80-class: ldmatrix / mma.sync / cp.async — base sm_103 legal)
// ---------------------------------------------------------------------------
__device__ __forceinline__ uint32_t smem_u32(const void* p) {
    uint32_t a;
    asm("{ .reg .u64 t; cvta.to.shared.u64 t, %1; cvt.u32.u64 %0, t; }"
        : "=r"(a) : "l"(p));
    return a;
}

__device__ __forceinline__ void ldm_x4(uint32_t* r, uint32_t addr) {
    asm volatile("ldmatrix.sync.aligned.m8n8.x4.shared.b16 {%0,%1,%2,%3}, [%4];"
                 : "=r"(r[0]), "=r"(r[1]), "=r"(r[2]), "=r"(r[3]) : "r"(addr));
}

__device__ __forceinline__ void mma_bf16(float* c, const uint32_t* a,
                                         uint32_t b0, uint32_t b1) {
    asm volatile(
        "mma.sync.aligned.m16n8k16.row.col.f32.bf16.bf16.f32 "
        "{%0,%1,%2,%3}, {%4,%5,%6,%7}, {%8,%9}, {%0,%1,%2,%3};"
        : "+f"(c[0]), "+f"(c[1]), "+f"(c[2]), "+f"(c[3])
        : "r"(a[0]), "r"(a[1]), "r"(a[2]), "r"(a[3]), "r"(b0), "r"(b1));
}

#define CP_ASYNC16(dst, src) \
    asm volatile("cp.async.cg.shared.global [%0], [%1], 16;" \
                 :: "r"(dst), "l"(src) : "memory")
#define CP_COMMIT()  asm volatile("cp.async.commit_group;" ::: "memory")
#define CP_WAIT(n)   asm volatile("cp.async.wait_group %0;" :: "n"(n) : "memory")

#define SW128(o) ((o) ^ (((o) >> 3) & 0x70))

// fp32 pair -> bf16x2 hi word + bf16x2 residual word
__device__ __forceinline__ void pack_split(float x, float y,
                                           uint32_t& hi, uint32_t& lo) {
    __nv_bfloat16 hx = __float2bfloat16(x);
    __nv_bfloat16 hy = __float2bfloat16(y);
    __nv_bfloat162 h2(hx, hy);
    hi = *(uint32_t*)&h2;
    __nv_bfloat162 l2(__float2bfloat16(x - __bfloat162float(hx)),
                      __float2bfloat16(y - __bfloat162float(hy)));
    lo = *(uint32_t*)&l2;
}

// ---------------------------------------------------------------------------
// Conversion kernels (fp32 -> bf16 hi/lo split)
// ---------------------------------------------------------------------------
__global__ void convert_split_kernel(const float* __restrict__ in,
                                     __nv_bfloat16* __restrict__ hi,
                                     __nv_bfloat16* __restrict__ lo, int n4)
{
    int i = blockIdx.x * blockDim.x + threadIdx.x;
    if (i >= n4) return;
    float4 v = ((const float4*)in)[i];
    uint32_t h0, l0, h1, l1;
    pack_split(v.x, v.y, h0, l0);
    pack_split(v.z, v.w, h1, l1);
    ((uint32_t*)hi)[2 * i]     = h0;
    ((uint32_t*)hi)[2 * i + 1] = h1;
    ((uint32_t*)lo)[2 * i]     = l0;
    ((uint32_t*)lo)[2 * i + 1] = l1;
}

// W [K][N] fp32  ->  Th/Tl [N][K] bf16 (transpose + split)
__global__ void transpose_split_kernel(const float* __restrict__ W,
                                       __nv_bfloat16* __restrict__ Th,
                                       __nv_bfloat16* __restrict__ Tl,
                                       int Kdim, int Ndim)
{
    __shared__ float tile[32][33];
    const int nx = blockIdx.x * 32 + threadIdx.x;
    const int ky = blockIdx.y * 32;
#pragma unroll
    for (int i = threadIdx.y; i < 32; i += 8)
        tile[i][threadIdx.x] = W[(size_t)(ky + i) * Ndim + nx];
    __syncthreads();
    const int k = ky + threadIdx.x;
#pragma unroll
    for (int i = threadIdx.y; i < 32; i += 8) {
        const int n = blockIdx.x * 32 + i;
        const float v = tile[threadIdx.x][i];
        __nv_bfloat16 h = __float2bfloat16(v);
        Th[(size_t)n * Kdim + k] = h;
        Tl[(size_t)n * Kdim + k] = __float2bfloat16(v - __bfloat162float(h));
    }
}

// ---------------------------------------------------------------------------
// mma.sync bf16-split3 GEMM: C[M,NTOT] = A[M,1024] @ B^T + bias
//   C = Ah*Bh + Ah*Bl + Al*Bh  (fp32 accumulate)
// CTA 128x128, BK=32, 256 threads (8 warps 4x2, warp tile 32x64),
// cp.async 2-stage pipeline, 80B padded smem rows, 2 CTAs/SM co-resident
// (barrier/load shadows of one CTA covered by the other's warps).
// MODE 0: fp32 out + bias.  MODE 1: QKV scatter -> pre-split flash operands.
// ---------------------------------------------------------------------------
#define TILE_B   10240               // 128 rows * 80 B
#define STAGE_B  (4 * TILE_B)        // Ah, Al, Bh, Bl
#define GEMM_SMEM (2 * STAGE_B)      // 81920 B (2 stages -> 2 CTAs/SM)

template <int NTOT, int MODE>
__global__ __launch_bounds__(256, 2)
void gemm_mma(const __nv_bfloat16* __restrict__ Ahg, const __nv_bfloat16* __restrict__ Alg,
              const __nv_bfloat16* __restrict__ Bhg, const __nv_bfloat16* __restrict__ Blg,
              const float* __restrict__ bias, float* __restrict__ out)
{
    extern __shared__ char smem[];
    const uint32_t sb = smem_u32(smem);
    const int tid = threadIdx.x;
    const int wid = tid >> 5, lane = tid & 31;
    const int wm = wid & 3, wn = wid >> 2;
    const int bn = blockIdx.x, bm = blockIdx.y;

    const __nv_bfloat16* srcs[4] = {Ahg, Alg, Bhg, Blg};

    float acc[2][8][4];
#pragma unroll
    for (int i = 0; i < 2; i++)
#pragma unroll
        for (int j = 0; j < 8; j++)
#pragma unroll
            for (int f = 0; f < 4; f++) acc[i][j][f] = 0.0f;

    const int r_ld[2]  = {tid >> 2, (tid + 256) >> 2};
    const int c_ld     = (tid & 3) * 16;   // byte col within 64B row

    auto issue_loads = [&](int kc, int st) {
#pragma unroll
        for (int t4 = 0; t4 < 4; t4++) {
            const size_t rb = (t4 < 2) ? (size_t)bm * 128 : (size_t)bn * 128;
            const __nv_bfloat16* src = srcs[t4] + rb * NC + kc * 32;
            const uint32_t dst = sb + st * STAGE_B + t4 * TILE_B;
#pragma unroll
            for (int u = 0; u < 2; u++) {
                const int r = r_ld[u];
                CP_ASYNC16(dst + r * 80 + c_ld,
                           (const char*)(src + (size_t)r * NC) + c_ld);
            }
        }
        CP_COMMIT();
    };

    issue_loads(0, 0);

    for (int kc = 0; kc < 32; kc++) {
        const int st = kc & 1;
        __syncthreads();                 // prior compute done before refilling st^1
        if (kc + 1 < 32) {
            issue_loads(kc + 1, st ^ 1);
            CP_WAIT(1);
        } else {
            CP_WAIT(0);
        }
        __syncthreads();

        const uint32_t stb = sb + st * STAGE_B;
        const uint32_t lrow = (lane & 15);
        const uint32_t lcol = (lane >> 4) * 16;

#pragma unroll
        for (int k16 = 0; k16 < 2; k16++) {
            const uint32_t koff = k16 * 32 + lcol;
            uint32_t aH[2][4], aL[2][4], bH[4][4], bL[4][4];
#pragma unroll
            for (int i = 0; i < 2; i++) {
                const uint32_t row = wm * 32 + i * 16 + lrow;
                ldm_x4(aH[i], stb + 0 * TILE_B + row * 80 + koff);
                ldm_x4(aL[i], stb + 1 * TILE_B + row * 80 + koff);
            }
#pragma unroll
            for (int j2 = 0; j2 < 4; j2++) {
                const uint32_t row = wn * 64 + j2 * 16 + lrow;
                ldm_x4(bH[j2], stb + 2 * TILE_B + row * 80 + koff);
                ldm_x4(bL[j2], stb + 3 * TILE_B + row * 80 + koff);
            }
#pragma unroll
            for (int i = 0; i < 2; i++)
#pragma unroll
                for (int j = 0; j < 8; j++) {
                    const int j2 = j >> 1, o = j & 1;
                    mma_bf16(acc[i][j], aH[i], bH[j2][o], bH[j2][o + 2]);
                    mma_bf16(acc[i][j], aH[i], bL[j2][o], bL[j2][o + 2]);
                    mma_bf16(acc[i][j], aL[i], bH[j2][o], bH[j2][o + 2]);
                }
        }
    }

    // Epilogue
    const int rr = lane >> 2;
    const int cc = (lane & 3) * 2;
#pragma unroll
    for (int i = 0; i < 2; i++) {
#pragma unroll
        for (int j = 0; j < 8; j++) {
            const int gc = bn * 128 + wn * 64 + j * 8 + cc;
            const float bz0 = bias[gc], bz1 = bias[gc + 1];
#pragma unroll
            for (int h2 = 0; h2 < 2; h2++) {
                const int gm = bm * 128 + wm * 32 + i * 16 + h2 * 8 + rr;
                const float v0 = acc[i][j][h2 * 2 + 0] + bz0;
                const float v1 = acc[i][j][h2 * 2 + 1] + bz1;
                if (MODE == 0) {
                    *(float2*)&out[(size_t)gm * NTOT + gc] = make_float2(v0, v1);
                } else {
                    const int part = gc >> 10;          // 0=q 1=k 2=v
                    const int h  = (gc & (NC - 1)) >> 6;
                    const int d0 = gc & 63;
                    const int b  = gm >> 11;
                    const int tt = gm & (NT - 1);
                    const int bh = b * NH + h;
                    if (part == 0) {
                        uint32_t hi, lo;
                        pack_split(v0 * QSCALE, v1 * QSCALE, hi, lo);
                        const size_t base = ((size_t)bh * NT + tt) * ND + d0;
                        *(uint32_t*)&g_qh[base] = hi;
                        *(uint32_t*)&g_ql[base] = lo;
                    } else if (part == 1) {
                        uint32_t hi, lo;
                        pack_split(v0, v1, hi, lo);
                        const size_t base = ((size_t)bh * NT + tt) * ND + d0;
                        *(uint32_t*)&g_kh[base] = hi;
                        *(uint32_t*)&g_kl[base] = lo;
                    } else {
                        const size_t base = ((size_t)bh * ND + d0) * NT + tt;
                        __nv_bfloat16 h0 = __float2bfloat16(v0);
                        __nv_bfloat16 h1 = __float2bfloat16(v1);
                        g_vTh[base]      = h0;
                        g_vTh[base + NT] = h1;
                        g_vTl[base]      = __float2bfloat16(v0 - __bfloat162float(h0));
                        g_vTl[base + NT] = __float2bfloat16(v1 - __bfloat162float(h1));
                    }
                }
            }
        }
    }
}

// ---------------------------------------------------------------------------
// Flash attention v2 (tensor-core, bf16 split-3 for S and PV, fp32 softmax)
// CTA: 128 q-rows x one bh. 256 threads = 8 warps, warp = 16 q-rows.
// K-tiles of 64 keys, double-buffered cp.async.  (unchanged from R10)
// ---------------------------------------------------------------------------
#define FL2_SMEM (32768 + 2 * 32768)   // 98304 B

__global__ __launch_bounds__(256, 1)
void flash2_kernel()
{
    extern __shared__ char smc[];
    const uint32_t sb = smem_u32(smc);
    const int tid = threadIdx.x;
    const int w = tid >> 5, lane = tid & 31;
    const int qt = blockIdx.x, bh = blockIdx.y;
    const int q0 = qt * 128;

    const __nv_bfloat16* Qh_g = g_qh + ((size_t)bh * NT + q0) * ND;
    const __nv_bfloat16* Ql_g = g_ql + ((size_t)bh * NT + q0) * ND;
    const __nv_bfloat16* Kh_g = g_kh + (size_t)bh * NT * ND;
    const __nv_bfloat16* Kl_g = g_kl + (size_t)bh * NT * ND;
    const __nv_bfloat16* Vh_g = g_vTh + (size_t)bh * ND * NT;
    const __nv_bfloat16* Vl_g = g_vTl + (size_t)bh * ND * NT;

    const uint32_t sQh = sb, sQl = sb + 16384;

    auto load_kv = [&](int jt, int st) {
        const int k0 = jt * 64;
        const uint32_t base = sb + 32768 + st * 32768;
#pragma unroll
        for (int u = 0; u < 2; u++) {
            const int idx = tid + u * 256;            // 0..511
            const int r = idx >> 3, c = (idx & 7) * 16;
            const uint32_t sw = SW128(r * 128 + c);
            CP_ASYNC16(base +         sw, (const char*)(Kh_g + (size_t)(k0 + r) * ND) + c);
            CP_ASYNC16(base +  8192 + sw, (const char*)(Kl_g + (size_t)(k0 + r) * ND) + c);
            CP_ASYNC16(base + 16384 + sw, (const char*)(Vh_g + (size_t)r * NT + k0) + c);
            CP_ASYNC16(base + 24576 + sw, (const char*)(Vl_g + (size_t)r * NT + k0) + c);
        }
        CP_COMMIT();
    };

    // Q tile load (with group 0)
#pragma unroll
    for (int u = 0; u < 4; u++) {
        const int idx = tid + u * 256;                // 0..1023
        const int r = idx >> 3, c = (idx & 7) * 16;
        const uint32_t sw = SW128(r * 128 + c);
        CP_ASYNC16(sQh + sw, (const char*)(Qh_g + (size_t)r * ND) + c);
        CP_ASYNC16(sQl + sw, (const char*)(Ql_g + (size_t)r * ND) + c);
    }
    load_kv(0, 0);
    load_kv(1, 1);

    const int nkt = 2 * qt + 2;
    const uint32_t lrow = lane & 15, lcolB = (lane >> 4) * 16;

    uint32_t qfh[4][4], qfl[4][4];
    float m0 = -1e30f, m1 = -1e30f, l0 = 0.0f, l1 = 0.0f;
    float o[8][4];
#pragma unroll
    for (int j = 0; j < 8; j++)
#pragma unroll
        for (int f = 0; f < 4; f++) o[j][f] = 0.0f;

    for (int jt = 0; jt < nkt; jt++) {
        const int st = jt & 1;
        if (jt + 1 < nkt) CP_WAIT(1); else CP_WAIT(0);
        __syncthreads();

        if (jt == 0) {
#pragma unroll
            for (int kt = 0; kt < 4; kt++) {
                const uint32_t off = SW128((w * 16 + lrow) * 128 + kt * 32 + lcolB);
                ldm_x4(qfh[kt], sQh + off);
                ldm_x4(qfl[kt], sQl + off);
            }
        }

        const bool diag0 = (jt == 2 * qt);
        const bool diag1 = (jt == 2 * qt + 1);
        const bool skip  = diag1 && (w < 4);    // fully masked sub-tile

        if (!skip) {
            const uint32_t kb = sb + 32768 + st * 32768;

            // S = Q K^T (split-3)
            float s[8][4];
#pragma unroll
            for (int j = 0; j < 8; j++)
#pragma unroll
                for (int f = 0; f < 4; f++) s[j][f] = 0.0f;

#pragma unroll
            for (int kt = 0; kt < 4; kt++) {
                uint32_t bKh[4][4], bKl[4][4];
#pragma unroll
                for (int j2 = 0; j2 < 4; j2++) {
                    const uint32_t off = SW128((j2 * 16 + lrow) * 128 + kt * 32 + lcolB);
                    ldm_x4(bKh[j2], kb + off);
                    ldm_x4(bKl[j2], kb + 8192 + off);
                }
#pragma unroll
                for (int j = 0; j < 8; j++) {
                    const int j2 = j >> 1, od = j & 1;
                    mma_bf16(s[j], qfh[kt], bKh[j2][od], bKh[j2][od + 2]);
                    mma_bf16(s[j], qfh[kt], bKl[j2][od], bKl[j2][od + 2]);
                    mma_bf16(s[j], qfl[kt], bKh[j2][od], bKh[j2][od + 2]);
                }
            }

            // causal mask on diagonal sub-tiles
            if ((diag0 && w < 4) || diag1) {
                const int qloc  = w * 16 + (lane >> 2);
                const int kbase = diag1 ? 64 : 0;
#pragma unroll
                for (int j = 0; j < 8; j++) {
                    const int kc = kbase + j * 8 + (lane & 3) * 2;
                    if (kc     > qloc)     s[j][0] = -1e30f;
                    if (kc + 1 > qloc)     s[j][1] = -1e30f;
                    if (kc     > qloc + 8) s[j][2] = -1e30f;
                    if (kc + 1 > qloc + 8) s[j][3] = -1e30f;
                }
            }

            // online softmax (exp2 domain; rows r=lane>>2 and r+8)
            float mx0 = -1e30f, mx1 = -1e30f;
#pragma unroll
            for (int j = 0; j < 8; j++) {
                mx0 = fmaxf(mx0, fmaxf(s[j][0], s[j][1]));
                mx1 = fmaxf(mx1, fmaxf(s[j][2], s[j][3]));
            }
            mx0 = fmaxf(mx0, __shfl_xor_sync(0xffffffffu, mx0, 1));
            mx0 = fmaxf(mx0, __shfl_xor_sync(0xffffffffu, mx0, 2));
            mx1 = fmaxf(mx1, __shfl_xor_sync(0xffffffffu, mx1, 1));
            mx1 = fmaxf(mx1, __shfl_xor_sync(0xffffffffu, mx1, 2));
            const float mn0 = fmaxf(m0, mx0), mn1 = fmaxf(m1, mx1);
            const float f0 = exp2f(m0 - mn0), f1 = exp2f(m1 - mn1);
            float rs0 = 0.0f, rs1 = 0.0f;
#pragma unroll
            for (int j = 0; j < 8; j++) {
                s[j][0] = exp2f(s[j][0] - mn0);
                s[j][1] = exp2f(s[j][1] - mn0);
                s[j][2] = exp2f(s[j][2] - mn1);
                s[j][3] = exp2f(s[j][3] - mn1);
                rs0 += s[j][0] + s[j][1];
                rs1 += s[j][2] + s[j][3];
            }
            rs0 += __shfl_xor_sync(0xffffffffu, rs0, 1);
            rs0 += __shfl_xor_sync(0xffffffffu, rs0, 2);
            rs1 += __shfl_xor_sync(0xffffffffu, rs1, 1);
            rs1 += __shfl_xor_sync(0xffffffffu, rs1, 2);
            l0 = l0 * f0 + rs0; m0 = mn0;
            l1 = l1 * f1 + rs1; m1 = mn1;
#pragma unroll
            for (int j = 0; j < 8; j++) {
                o[j][0] *= f0; o[j][1] *= f0;
                o[j][2] *= f1; o[j][3] *= f1;
            }

            // repack P (C-frag -> A-frag), split hi/lo
            uint32_t ph[4][4], pl[4][4];
#pragma unroll
            for (int kt = 0; kt < 4; kt++) {
                pack_split(s[2 * kt][0],     s[2 * kt][1],     ph[kt][0], pl[kt][0]);
                pack_split(s[2 * kt][2],     s[2 * kt][3],     ph[kt][1], pl[kt][1]);
                pack_split(s[2 * kt + 1][0], s[2 * kt + 1][1], ph[kt][2], pl[kt][2]);
                pack_split(s[2 * kt + 1][2], s[2 * kt + 1][3], ph[kt][3], pl[kt][3]);
            }

            // O += P V (split-3), B = V^T smem [d][key]
            const uint32_t vb = kb + 16384;
#pragma unroll
            for (int kt = 0; kt < 4; kt++) {
                uint32_t bVh[4][4], bVl[4][4];
#pragma unroll
                for (int j2 = 0; j2 < 4; j2++) {
                    const uint32_t off = SW128((j2 * 16 + lrow) * 128 + kt * 32 + lcolB);
                    ldm_x4(bVh[j2], vb + off);
                    ldm_x4(bVl[j2], vb + 8192 + off);
                }
#pragma unroll
                for (int j = 0; j < 8; j++) {
                    const int j2 = j >> 1, od = j & 1;
                    mma_bf16(o[j], ph[kt], bVh[j2][od], bVh[j2][od + 2]);
                    mma_bf16(o[j], ph[kt], bVl[j2][od], bVl[j2][od + 2]);
                    mma_bf16(o[j], pl[kt], bVh[j2][od], bVh[j2][od + 2]);
                }
            }
        }

        __syncthreads();
        if (jt + 2 < nkt) load_kv(jt + 2, st);
    }

    // Epilogue: normalize, split, write g_atth/g_attl [B,T,C]
    const int b = bh >> 4, h = bh & 15;
    const int r0g = q0 + w * 16 + (lane >> 2);
    const float inv0 = 1.0f / l0, inv1 = 1.0f / l1;
#pragma unroll
    for (int j = 0; j < 8; j++) {
        const int dc = j * 8 + (lane & 3) * 2;
        const size_t base = ((size_t)(b * NT + r0g)) * NC + h * 64 + dc;
        uint32_t hi, lo;
        pack_split(o[j][0] * inv0, o[j][1] * inv0, hi, lo);
        *(uint32_t*)&g_atth[base] = hi;
        *(uint32_t*)&g_attl[base] = lo;
        pack_split(o[j][2] * inv1, o[j][3] * inv1, hi, lo);
        *(uint32_t*)&g_atth[base + 8 * NC] = hi;
        *(uint32_t*)&g_attl[base + 8 * NC] = lo;
    }
}

// ---------------------------------------------------------------------------
// kernel_launch
// ---------------------------------------------------------------------------
extern "C" void kernel_launch(void* const* d_in, const int* in_sizes, int n_in,
                              void* d_out, int out_size)
{
    const float* x     = (const float*)d_in[0];
    const float* w_qkv = (const float*)d_in[1];
    const float* b_qkv = (const float*)d_in[2];
    const float* w_out = (const float*)d_in[3];
    const float* b_out = (const float*)d_in[4];
    float* out = (float*)d_out;

    cudaFuncSetAttribute((const void*)flash2_kernel,
                         cudaFuncAttributeMaxDynamicSharedMemorySize, FL2_SMEM);
    cudaFuncSetAttribute((const void*)gemm_mma<NQKV, 1>,
                         cudaFuncAttributeMaxDynamicSharedMemorySize, GEMM_SMEM);
    cudaFuncSetAttribute((const void*)gemm_mma<NC, 0>,
                         cudaFuncAttributeMaxDynamicSharedMemorySize, GEMM_SMEM);

    void *p_ah, *p_al, *p_wqh, *p_wql, *p_woh, *p_wol, *p_atth, *p_attl;
    cudaGetSymbolAddress(&p_ah,   g_ah);
    cudaGetSymbolAddress(&p_al,   g_al);
    cudaGetSymbolAddress(&p_wqh,  g_wqT_h);
    cudaGetSymbolAddress(&p_wql,  g_wqT_l);
    cudaGetSymbolAddress(&p_woh,  g_woT_h);
    cudaGetSymbolAddress(&p_wol,  g_woT_l);
    cudaGetSymbolAddress(&p_atth, g_atth);
    cudaGetSymbolAddress(&p_attl, g_attl);

    const int n4 = NM * NC / 4;

    // 1) Split x, transpose+split weights
    convert_split_kernel<<<(n4 + 255) / 256, 256>>>(
        x, (__nv_bfloat16*)p_ah, (__nv_bfloat16*)p_al, n4);
    transpose_split_kernel<<<dim3(NQKV / 32, NC / 32), dim3(32, 8)>>>(
        w_qkv, (__nv_bfloat16*)p_wqh, (__nv_bfloat16*)p_wql, NC, NQKV);
    transpose_split_kernel<<<dim3(NC / 32, NC / 32), dim3(32, 8)>>>(
        w_out, (__nv_bfloat16*)p_woh, (__nv_bfloat16*)p_wol, NC, NC);

    // 2) QKV projection -> pre-split bf16 flash operands
    gemm_mma<NQKV, 1><<<dim3(NQKV / 128, NM / 128), 256, GEMM_SMEM>>>(
        (const __nv_bfloat16*)p_ah, (const __nv_bfloat16*)p_al,
        (const __nv_bfloat16*)p_wqh, (const __nv_bfloat16*)p_wql,
        b_qkv, nullptr);

    // 3) Tensor-core causal flash attention -> g_atth/g_attl
    flash2_kernel<<<dim3(NT / 128, NB * NH), 256, FL2_SMEM>>>();

    // 4) Output projection
    gemm_mma<NC, 0><<<dim3(NC / 128, NM / 128), 256, GEMM_SMEM>>>(
        (const __nv_bfloat16*)p_atth, (const __nv_bfloat16*)p_attl,
        (const __nv_bfloat16*)p_woh, (const __nv_bfloat16*)p_wol,
        b_out, out);
}